// round 1
// baseline (speedup 1.0000x reference)
#include <cuda_runtime.h>
#include <math.h>

// ---------------- static device scratch (no allocation allowed) ----------------
#define MAXM 25088          // 256*98
__device__ float g_xa[MAXM * 512];
__device__ float g_xb[MAXM * 512];
__device__ float g_at[MAXM * 512];
__device__ float g_tp[MAXM * 512];
__device__ float g_qk[MAXM * 1536];
__device__ float g_hd[MAXM * 1024];
__device__ float g_wc[2 * 1536 * 512];     // conv weights pre-transposed [(l,tap,d_in), d_out]
__device__ float g_ct[512 * 8192];         // codebook transposed [d][k]
__device__ float g_cn[8192];               // ||c||^2
__device__ float g_sc[12544 * 8192];       // VQ scores

__device__ __forceinline__ float gelu_f(float x) {
    return 0.5f * x * (1.0f + erff(x * 0.7071067811865476f));
}

// ---------------- weight prep ----------------
__global__ void tr_convw(const float* __restrict__ w, float* __restrict__ wc) {
    int id = blockIdx.x * 256 + threadIdx.x;
    if (id >= 2 * 1536 * 512) return;
    int o  = id & 511;
    int kk = (id >> 9) % 1536;
    int l  = id / (1536 * 512);
    int tap = kk / 512, i = kk & 511;
    wc[id] = w[(((size_t)l * 512 + o) * 512 + i) * 3 + tap];
}

__global__ void tr_cb(const float* __restrict__ cb, float* __restrict__ cbT) {
    __shared__ float t[32][33];
    int n0 = blockIdx.x * 32, d0 = blockIdx.y * 32;
    for (int i = threadIdx.y; i < 32; i += 8)
        t[i][threadIdx.x] = cb[(size_t)(n0 + i) * 512 + d0 + threadIdx.x];
    __syncthreads();
    for (int i = threadIdx.y; i < 32; i += 8)
        cbT[(size_t)(d0 + i) * 8192 + n0 + threadIdx.x] = t[threadIdx.x][i];
}

__global__ void cnorm_k(const float* __restrict__ cb, float* __restrict__ cn) {
    int warp = threadIdx.x >> 5, lane = threadIdx.x & 31;
    int row = blockIdx.x * 8 + warp;
    const float* rp = cb + (size_t)row * 512;
    float s = 0.f;
#pragma unroll
    for (int c = 0; c < 4; c++) {
        float4 v = *(const float4*)(rp + lane * 4 + c * 128);
        s += v.x * v.x + v.y * v.y + v.z * v.z + v.w * v.w;
    }
#pragma unroll
    for (int o = 16; o; o >>= 1) s += __shfl_xor_sync(0xffffffffu, s, o);
    if (!lane) cn[row] = s;
}

// ---------------- generic tiled fp32 GEMM ----------------
// C[M,N] = A[M,Kd] @ Bw[Kd,N]  (+ epilogue)
// EPI: 0 = +bias | 1 = +bias,relu | 2 = +bias,gelu | 3 = +bias,+res | 4 = bias[n] - 2*acc (VQ)
// GATHER: A is gathered from x[B,Tin,512] with 3-tap stride-2 causal conv indexing (Kd=1536)
template<int EPI, bool GATHER>
__global__ __launch_bounds__(256) void gemm_k(
    const float* __restrict__ A, const float* __restrict__ Bw,
    const float* __restrict__ bias, const float* __restrict__ res,
    float* __restrict__ C, int M, int N, int Kd, int Tin, int Tout)
{
    __shared__ float As[16][132];   // stored transposed: As[k][m], row stride 528B (16B mult)
    __shared__ float Bs[16][64];
    int tid = threadIdx.x;
    int tx = tid & 15, ty = tid >> 4;
    int row0 = blockIdx.y * 128;
    int col0 = blockIdx.x * 64;
    int kq = (tid & 3) * 4;
    int ar = tid >> 2;
    int bn = (tid & 15) * 4;
    int bk = tid >> 4;
    float acc[8][4];
#pragma unroll
    for (int i = 0; i < 8; i++)
#pragma unroll
        for (int j = 0; j < 4; j++) acc[i][j] = 0.f;

    for (int k0 = 0; k0 < Kd; k0 += 16) {
#pragma unroll
        for (int hh = 0; hh < 2; hh++) {
            int r = row0 + ar + hh * 64;
            int kk = k0 + kq;
            float4 v;
            if (GATHER) {
                int b2 = r / Tout;
                int t  = r - b2 * Tout;
                int tap = kk >> 9, d = kk & 511;
                int fr = 2 * t + tap - 2;
                if (fr < 0) fr = 0;
                v = *(const float4*)(A + ((size_t)(b2 * Tin + fr) * 512 + d));
            } else {
                v = *(const float4*)(A + (size_t)r * Kd + kk);
            }
            As[kq + 0][ar + hh * 64] = v.x;
            As[kq + 1][ar + hh * 64] = v.y;
            As[kq + 2][ar + hh * 64] = v.z;
            As[kq + 3][ar + hh * 64] = v.w;
        }
        *(float4*)&Bs[bk][bn] = *(const float4*)(Bw + (size_t)(k0 + bk) * N + col0 + bn);
        __syncthreads();
#pragma unroll
        for (int k = 0; k < 16; k++) {
            float a[8], bv[4];
#pragma unroll
            for (int i = 0; i < 8; i++) a[i] = As[k][ty * 8 + i];
#pragma unroll
            for (int j = 0; j < 4; j++) bv[j] = Bs[k][tx * 4 + j];
#pragma unroll
            for (int i = 0; i < 8; i++)
#pragma unroll
                for (int j = 0; j < 4; j++) acc[i][j] += a[i] * bv[j];
        }
        __syncthreads();
    }

#pragma unroll
    for (int i = 0; i < 8; i++) {
        size_t r = (size_t)row0 + ty * 8 + i;
        int n = col0 + tx * 4;
        size_t cidx = r * (size_t)N + n;
        float v[4];
#pragma unroll
        for (int j = 0; j < 4; j++) {
            if (EPI == 4) v[j] = bias[n + j] - 2.f * acc[i][j];
            else          v[j] = acc[i][j] + bias[n + j];
        }
        if (EPI == 1) {
#pragma unroll
            for (int j = 0; j < 4; j++) v[j] = fmaxf(v[j], 0.f);
        }
        if (EPI == 2) {
#pragma unroll
            for (int j = 0; j < 4; j++) v[j] = gelu_f(v[j]);
        }
        if (EPI == 3) {
            float4 rv = *(const float4*)(res + cidx);
            v[0] += rv.x; v[1] += rv.y; v[2] += rv.z; v[3] += rv.w;
        }
        *(float4*)(C + cidx) = make_float4(v[0], v[1], v[2], v[3]);
    }
}

// ---------------- causal attention (one block per (b,h)) ----------------
__global__ __launch_bounds__(256) void attn_kernel(const float* __restrict__ qkv,
                                                   float* __restrict__ out, int T) {
    extern __shared__ float smx[];
    float* Vs = smx;                 // T * 132 (float4-aligned base)
    float* Ks = Vs + T * 132;        // T * 129
    float* qs = Ks + T * 129;        // 8 * 128
    float* ps = qs + 8 * 128;        // 8 * 100
    int tid = threadIdx.x;
    int bh = blockIdx.x;
    int b = bh >> 2, h = bh & 3;
    const float* base = qkv + (size_t)b * T * 1536 + h * 128;

    for (int idx = tid; idx < T * 128; idx += 256) {
        int j = idx >> 7, d = idx & 127;
        const float* rowp = base + (size_t)j * 1536;
        Ks[j * 129 + d] = rowp[512 + d];
        Vs[j * 132 + d] = rowp[1024 + d];
    }
    __syncthreads();

    int warp = tid >> 5, lane = tid & 31;
    float* qw = qs + warp * 128;
    float* pw = ps + warp * 100;
    const float scale = 0.08838834764831845f;  // 1/sqrt(128)

    for (int i = warp; i < T; i += 8) {
        const float* qrow = base + (size_t)i * 1536;
#pragma unroll
        for (int c = 0; c < 4; c++) qw[lane + 32 * c] = qrow[lane + 32 * c];
        __syncwarp();
        float mx = -1e30f;
        for (int j = lane; j <= i; j += 32) {
            float s = 0.f;
            const float* kr = Ks + j * 129;
#pragma unroll 8
            for (int d = 0; d < 128; d++) s += qw[d] * kr[d];
            s *= scale;
            pw[j] = s;
            if (s > mx) mx = s;
        }
#pragma unroll
        for (int o = 16; o; o >>= 1) mx = fmaxf(mx, __shfl_xor_sync(0xffffffffu, mx, o));
        float sum = 0.f;
        for (int j = lane; j <= i; j += 32) {
            float e = expf(pw[j] - mx);
            pw[j] = e;
            sum += e;
        }
#pragma unroll
        for (int o = 16; o; o >>= 1) sum += __shfl_xor_sync(0xffffffffu, sum, o);
        float inv = 1.f / sum;
        __syncwarp();
        float4 acc = make_float4(0.f, 0.f, 0.f, 0.f);
        for (int j = 0; j <= i; j++) {
            float p = pw[j];
            float4 v = *(const float4*)(Vs + j * 132 + lane * 4);
            acc.x += p * v.x; acc.y += p * v.y; acc.z += p * v.z; acc.w += p * v.w;
        }
        acc.x *= inv; acc.y *= inv; acc.z *= inv; acc.w *= inv;
        *(float4*)(out + (size_t)(b * T + i) * 512 + h * 128 + lane * 4) = acc;
        __syncwarp();
    }
}

// ---------------- layernorm (one block of 128 threads per row) ----------------
__global__ __launch_bounds__(128) void ln_k(const float* __restrict__ in,
                                            const float* __restrict__ g,
                                            const float* __restrict__ bb,
                                            float* __restrict__ out) {
    __shared__ float red[4];
    int row = blockIdx.x, tid = threadIdx.x;
    const float4 x = *(const float4*)(in + (size_t)row * 512 + tid * 4);
    float s = x.x + x.y + x.z + x.w;
#pragma unroll
    for (int o = 16; o; o >>= 1) s += __shfl_xor_sync(0xffffffffu, s, o);
    if ((tid & 31) == 0) red[tid >> 5] = s;
    __syncthreads();
    float mean = (red[0] + red[1] + red[2] + red[3]) * 0.001953125f;
    float a0 = x.x - mean, a1 = x.y - mean, a2 = x.z - mean, a3 = x.w - mean;
    float q = a0 * a0 + a1 * a1 + a2 * a2 + a3 * a3;
#pragma unroll
    for (int o = 16; o; o >>= 1) q += __shfl_xor_sync(0xffffffffu, q, o);
    __syncthreads();
    if ((tid & 31) == 0) red[tid >> 5] = q;
    __syncthreads();
    float var = (red[0] + red[1] + red[2] + red[3]) * 0.001953125f;
    float rs = rsqrtf(var + 1e-5f);
    float4 gv = *(const float4*)(g + tid * 4);
    float4 bv = *(const float4*)(bb + tid * 4);
    float4 o4 = make_float4(a0 * rs * gv.x + bv.x, a1 * rs * gv.y + bv.y,
                            a2 * rs * gv.z + bv.z, a3 * rs * gv.w + bv.w);
    *(float4*)(out + (size_t)row * 512 + tid * 4) = o4;
}

// ---------------- VQ argmin + gather ----------------
__global__ __launch_bounds__(256) void vq_fin(const float* __restrict__ sc,
                                              const float* __restrict__ cb,
                                              float* __restrict__ oq,
                                              float* __restrict__ oi) {
    __shared__ unsigned long long sm[256];
    int row = blockIdx.x, tid = threadIdx.x;
    const float* sr = sc + (size_t)row * 8192;
    unsigned long long best = ~0ull;
    for (int n = tid; n < 8192; n += 256) {
        float s = sr[n];
        unsigned int ub = __float_as_uint(s);
        ub = (ub & 0x80000000u) ? ~ub : (ub | 0x80000000u);
        unsigned long long key = ((unsigned long long)ub << 32) | (unsigned int)n;
        if (key < best) best = key;
    }
    sm[tid] = best;
    __syncthreads();
    for (int off = 128; off; off >>= 1) {
        if (tid < off && sm[tid + off] < sm[tid]) sm[tid] = sm[tid + off];
        __syncthreads();
    }
    int idx = (int)(sm[0] & 0xffffffffu);
    const float* crow = cb + (size_t)idx * 512;
    float* qrow = oq + (size_t)row * 512;
    for (int d = tid; d < 512; d += 256) qrow[d] = crow[d];
    if (tid == 0 && oi) oi[row] = (float)idx;
}

// ---------------- host launch ----------------
extern "C" void kernel_launch(void* const* d_in, const int* in_sizes, int n_in,
                              void* d_out, int out_size) {
    const float* motion = (const float*)d_in[0];
    const float* conv_w = (const float*)d_in[1];
    const float* conv_b = (const float*)d_in[2];
    const float* wqkv   = (const float*)d_in[3];
    const float* bqkv   = (const float*)d_in[4];
    const float* wo     = (const float*)d_in[5];
    const float* bo     = (const float*)d_in[6];
    const float* ln1g   = (const float*)d_in[7];
    const float* ln1b   = (const float*)d_in[8];
    const float* ln2g   = (const float*)d_in[9];
    const float* ln2b   = (const float*)d_in[10];
    const float* w1     = (const float*)d_in[11];
    const float* b1     = (const float*)d_in[12];
    const float* w2     = (const float*)d_in[13];
    const float* b2     = (const float*)d_in[14];
    const float* cbook  = (const float*)d_in[15];

    float *xa, *xb, *at, *tp, *qk, *hd, *wc, *ct, *cn, *sc;
    cudaGetSymbolAddress((void**)&xa, g_xa);
    cudaGetSymbolAddress((void**)&xb, g_xb);
    cudaGetSymbolAddress((void**)&at, g_at);
    cudaGetSymbolAddress((void**)&tp, g_tp);
    cudaGetSymbolAddress((void**)&qk, g_qk);
    cudaGetSymbolAddress((void**)&hd, g_hd);
    cudaGetSymbolAddress((void**)&wc, g_wc);
    cudaGetSymbolAddress((void**)&ct, g_ct);
    cudaGetSymbolAddress((void**)&cn, g_cn);
    cudaGetSymbolAddress((void**)&sc, g_sc);

    cudaFuncSetAttribute(attn_kernel, cudaFuncAttributeMaxDynamicSharedMemorySize, 120 * 1024);

    // weight / codebook prep
    tr_convw<<<(2 * 1536 * 512 + 255) / 256, 256>>>(conv_w, wc);
    tr_cb<<<dim3(8192 / 32, 512 / 32), dim3(32, 8)>>>(cbook, ct);
    cnorm_k<<<8192 / 8, 256>>>(cbook, cn);

    const float* px = motion;
    int Tin = 196;
    float* bufs[2] = {xa, xb};
    for (int l = 0; l < 2; l++) {
        int Tout = Tin >> 1;
        int M = 256 * Tout;
        float* cx = bufs[l];
        // causal half-downsample conv (implicit gather GEMM, Kd=1536) + bias + exact GELU
        gemm_k<2, true><<<dim3(512 / 64, M / 128), 256>>>(
            px, wc + (size_t)l * 1536 * 512, conv_b + l * 512, nullptr, cx, M, 512, 1536, Tin, Tout);
        // QKV projection
        gemm_k<0, false><<<dim3(1536 / 64, M / 128), 256>>>(
            cx, wqkv + (size_t)l * 512 * 1536, bqkv + l * 1536, nullptr, qk, M, 1536, 512, 0, 0);
        // causal attention
        size_t smem = (size_t)(Tout * 132 + Tout * 129 + 8 * 128 + 8 * 100) * 4;
        attn_kernel<<<256 * 4, 256, smem>>>(qk, at, Tout);
        // output proj + residual
        gemm_k<3, false><<<dim3(512 / 64, M / 128), 256>>>(
            at, wo + (size_t)l * 512 * 512, bo + l * 512, cx, tp, M, 512, 512, 0, 0);
        ln_k<<<M, 128>>>(tp, ln1g + l * 512, ln1b + l * 512, cx);
        // FFN
        gemm_k<1, false><<<dim3(1024 / 64, M / 128), 256>>>(
            cx, w1 + (size_t)l * 512 * 1024, b1 + l * 1024, nullptr, hd, M, 1024, 512, 0, 0);
        gemm_k<3, false><<<dim3(512 / 64, M / 128), 256>>>(
            hd, w2 + (size_t)l * 1024 * 512, b2 + l * 512, cx, tp, M, 512, 1024, 0, 0);
        ln_k<<<M, 128>>>(tp, ln2g + l * 512, ln2b + l * 512, cx);
        px = cx;
        Tin = Tout;
    }

    // VQ: scores = ||c||^2 - 2 x.c   (||x||^2 constant per row, irrelevant to argmin)
    gemm_k<4, false><<<dim3(8192 / 64, 12544 / 128), 256>>>(
        px, ct, cn, nullptr, sc, 12544, 8192, 512, 0, 0);

    float* out = (float*)d_out;
    float* oidx = (out_size >= 12544 * 512 + 12544) ? out + (size_t)12544 * 512 : nullptr;
    vq_fin<<<12544, 256>>>(sc, cbook, out, oidx);
}